// round 17
// baseline (speedup 1.0000x reference)
#include <cuda_runtime.h>
#include <cuda_bf16.h>
#include <math.h>
#include <stdint.h>

#define HID 128
#define NLV 262144
#define NCTA 128
#define NT 1024

// ---------------- device buffers (static = allocation-guard safe) ----------------
__device__ __nv_bfloat16 g_Ahi[(size_t)65536 * 256];    // 32 MB (P ping)
__device__ __nv_bfloat16 g_Alo[(size_t)65536 * 256];    // 32 MB
__device__ __nv_bfloat16 g_Bhi[(size_t)16384 * 256];    //  8 MB (P pong)
__device__ __nv_bfloat16 g_Blo[(size_t)16384 * 256];    //  8 MB
__device__ __nv_bfloat16 g_WLhi[256 * 128], g_WLlo[256 * 128];  // vstack(W_l,W_r)
__device__ __nv_bfloat16 g_WIhi[64 * 128],  g_WIlo[64 * 128];   // W_in
__device__ float g_bsum[128];
__device__ float g_bin[128];
__device__ unsigned g_bar_count;
__device__ unsigned g_bar_sense;

// ---------------- helpers ----------------
__device__ __forceinline__ uint32_t f2bf2(float a, float b) {
    uint32_t r;
    asm("cvt.rn.bf16x2.f32 %0, %1, %2;" : "=r"(r) : "f"(b), "f"(a));
    return r;
}
__device__ __forceinline__ float bf_lo(uint32_t p) { return __uint_as_float(p << 16); }
__device__ __forceinline__ float bf_hi(uint32_t p) { return __uint_as_float(p & 0xFFFF0000u); }

// Exact-formula fast tanh: 1 - 2/(e^{2x}+1); ~5 instr, abs err ~1e-7, inf-safe.
__device__ __forceinline__ float fast_tanh(float x) {
    float e = __expf(2.0f * x);
    return 1.0f - __fdividef(2.0f, e + 1.0f);
}

__device__ __forceinline__ void ldm_x4(uint32_t* r, uint32_t addr) {
    asm volatile("ldmatrix.sync.aligned.m8n8.x4.shared.b16 {%0,%1,%2,%3}, [%4];"
                 : "=r"(r[0]), "=r"(r[1]), "=r"(r[2]), "=r"(r[3]) : "r"(addr));
}
__device__ __forceinline__ void ldm_x4_t(uint32_t* r, uint32_t addr) {
    asm volatile("ldmatrix.sync.aligned.m8n8.x4.trans.shared.b16 {%0,%1,%2,%3}, [%4];"
                 : "=r"(r[0]), "=r"(r[1]), "=r"(r[2]), "=r"(r[3]) : "r"(addr));
}
__device__ __forceinline__ void mma_bf16(float* c, const uint32_t* a, const uint32_t* b) {
    asm volatile("mma.sync.aligned.m16n8k16.row.col.f32.bf16.bf16.f32 "
                 "{%0,%1,%2,%3}, {%4,%5,%6,%7}, {%8,%9}, {%0,%1,%2,%3};"
                 : "+f"(c[0]), "+f"(c[1]), "+f"(c[2]), "+f"(c[3])
                 : "r"(a[0]), "r"(a[1]), "r"(a[2]), "r"(a[3]), "r"(b[0]), "r"(b[1]));
}
__device__ __forceinline__ void cp16(uint32_t dst, const void* src) {
    asm volatile("cp.async.ca.shared.global [%0], [%1], 16;" :: "r"(dst), "l"(src));
}
#define CP_COMMIT() asm volatile("cp.async.commit_group;" ::: "memory")
#define CP_WAIT(N)  asm volatile("cp.async.wait_group %0;" :: "n"(N) : "memory")

// SWZA: A tiles, 128B rows. SWZW: W, 256B rows. SWZB: smem P, 512B rows.
#define SWZA(o) ((o) ^ ((((uint32_t)(o)) >> 3) & 0x70))
#define SWZW(o) ((o) ^ (((((uint32_t)(o)) >> 8) & 7) << 4))
#define SWZB(o) ((o) ^ (((((uint32_t)(o)) >> 9) & 7) << 4))

// ---------------- smem layout ----------------
#define SM_BIN  0
#define SM_BSUM 512
#define SM_W    1024
#define W_LO_OFF 65536
#define SM_S0   (1024 + 131072)
#define SM_S1   (SM_S0 + 32768)
#define SM_S2   (SM_S1 + 32768)
#define SMEM_ALL (SM_S2 + 32768)    // 230400 B

// ---------------- grid barrier (all 128 CTAs resident, 1/SM) ----------------
__device__ __forceinline__ void grid_barrier(unsigned b) {
    __syncthreads();
    if (threadIdx.x == 0) {
        __threadfence();
        unsigned arrived = atomicAdd(&g_bar_count, 1u);
        if (arrived == NCTA - 1) {
            g_bar_count = 0;
            asm volatile("st.release.gpu.global.u32 [%0], %1;"
                         :: "l"(&g_bar_sense), "r"(b) : "memory");
        } else {
            unsigned s;
            do {
                asm volatile("ld.acquire.gpu.global.u32 %0, [%1];"
                             : "=r"(s) : "l"(&g_bar_sense) : "memory");
                if (s < b) __nanosleep(64);
            } while (s < b);
        }
    }
    __syncthreads();
}

// ---------------- prep ----------------
__global__ void prep_kernel(const float* __restrict__ W_in, const float* __restrict__ b_in,
                            const float* __restrict__ W_l, const float* __restrict__ b_l,
                            const float* __restrict__ W_r, const float* __restrict__ b_r) {
    int t = blockIdx.x * blockDim.x + threadIdx.x;
    int stride = gridDim.x * blockDim.x;
    if (t == 0) { g_bar_count = 0; g_bar_sense = 0; }
    for (int idx = t; idx < 256 * 128; idx += stride) {
        float w = (idx < 128 * 128) ? W_l[idx] : W_r[idx - 128 * 128];
        __nv_bfloat16 h = __float2bfloat16(w);
        g_WLhi[idx] = h;
        g_WLlo[idx] = __float2bfloat16(w - __bfloat162float(h));
    }
    for (int idx = t; idx < 64 * 128; idx += stride) {
        float w = W_in[idx];
        __nv_bfloat16 h = __float2bfloat16(w);
        g_WIhi[idx] = h;
        g_WIlo[idx] = __float2bfloat16(w - __bfloat162float(h));
    }
    if (t < 128) { g_bsum[t] = b_l[t] + b_r[t]; g_bin[t] = b_in[t]; }
}

// ---------------- persistent fused kernel: 1024 threads, 32 warps ----------------
__global__ void __launch_bounds__(NT, 1)
rnn_all(const float* __restrict__ leafX, float* __restrict__ out) {
    extern __shared__ char smem[];
    const uint32_t sb = (uint32_t)__cvta_generic_to_shared(smem);
    const int tid = threadIdx.x, l = tid & 31, wid = tid >> 5;
    const int wm = wid & 7, wn = wid >> 3;      // GEMM1: 8m x 4n, warp 16x32
    const int wm2 = wid >> 3, wn2 = wid & 7;    // GEMM2: 4m x 8n, warp 16x16
    const int cta = blockIdx.x;

    // ---- resident Wcat hi/lo ----
    for (int i = tid; i < 256 * 16; i += NT) {
        int kr = i >> 4, ch = i & 15;
        uint32_t off = SWZW((uint32_t)(kr * 256 + ch * 16));
        cp16(sb + SM_W + off, g_WLhi + (size_t)kr * 128 + ch * 8);
        cp16(sb + SM_W + W_LO_OFF + off, g_WLlo + (size_t)kr * 128 + ch * 8);
    }
    CP_COMMIT();
    if (tid < 128) {
        ((float*)(smem + SM_BIN))[tid]  = g_bin[tid];
        ((float*)(smem + SM_BSUM))[tid] = g_bsum[tid];
    }
    CP_WAIT(0);
    __syncthreads();

    // ---- GEMM1: one 64-wide K stage; warp 16 rows x 32 cols ----
    auto compute_stage1 = [&](float (*acc)[4], uint32_t abase, uint32_t wbase,
                              uint32_t wloff, int st) {
        #pragma unroll
        for (int ks = 0; ks < 4; ks++) {
            uint32_t ah[4], al[4], bh[4][2], bl[4][2];
            {
                int row = wm * 16 + (l & 15);
                uint32_t aoff = SWZA((uint32_t)(row * 128 + ks * 32 + (l >> 4) * 16));
                ldm_x4(ah, abase + aoff);
                ldm_x4(al, abase + 16384 + aoff);
            }
            #pragma unroll
            for (int ntp = 0; ntp < 2; ntp++) {
                int krow = st * 64 + ks * 16 + (l & 15);
                int nb   = (wn * 32 + ntp * 16 + (l >> 4) * 8) * 2;
                uint32_t woff = SWZW((uint32_t)(krow * 256 + nb));
                uint32_t t4[4];
                ldm_x4_t(t4, wbase + woff);
                bh[ntp * 2][0] = t4[0]; bh[ntp * 2][1] = t4[1];
                bh[ntp * 2 + 1][0] = t4[2]; bh[ntp * 2 + 1][1] = t4[3];
                ldm_x4_t(t4, wbase + wloff + woff);
                bl[ntp * 2][0] = t4[0]; bl[ntp * 2][1] = t4[1];
                bl[ntp * 2 + 1][0] = t4[2]; bl[ntp * 2 + 1][1] = t4[3];
            }
            #pragma unroll
            for (int nt = 0; nt < 4; nt++) mma_bf16(acc[nt], ah, bh[nt]);
            #pragma unroll
            for (int nt = 0; nt < 4; nt++) mma_bf16(acc[nt], ah, bl[nt]);
            #pragma unroll
            for (int nt = 0; nt < 4; nt++) mma_bf16(acc[nt], al, bh[nt]);
        }
    };

    // ---- epilogue1: bias+tanh H(128 rows) -> smem P (64 rows x 512B, SWZB) ----
    auto epilogue1 = [&](float (*acc)[4], const float* sBias) {
        #pragma unroll
        for (int nt = 0; nt < 4; nt++) {
            int c = wn * 32 + nt * 8 + (l & 3) * 2;
            #pragma unroll
            for (int half = 0; half < 2; half++) {
                int gm = wm * 16 + (l >> 2) + half * 8;
                float x0 = acc[nt][half * 2]     + sBias[c];
                float x1 = acc[nt][half * 2 + 1] + sBias[c + 1];
                float t0 = fast_tanh(x0), t1 = fast_tanh(x1);
                uint32_t hp = f2bf2(t0, t1);
                uint32_t lp = f2bf2(t0 - bf_lo(hp), t1 - bf_hi(hp));
                uint32_t off = SWZB((uint32_t)((gm >> 1) * 512 + ((gm & 1) * 128 + c) * 2));
                *(uint32_t*)(smem + SM_S1 + off) = hp;
                *(uint32_t*)(smem + SM_S2 + off) = lp;
            }
        }
    };

    // ---- GEMM2: up to 64 rows x 128, K=256; warp 16 rows x 16 cols ----
    auto compute_g2 = [&](float (*acc2)[4], int mrows) {
        if (wm2 * 16 >= mrows) return;
        #pragma unroll 4
        for (int ks2 = 0; ks2 < 16; ks2++) {
            uint32_t ah[4], al[4], bh[2][2], bl[2][2];
            {
                int row = wm2 * 16 + (l & 15);
                uint32_t aoff = SWZB((uint32_t)(row * 512 + ks2 * 32 + (l >> 4) * 16));
                ldm_x4(ah, sb + SM_S1 + aoff);
                ldm_x4(al, sb + SM_S2 + aoff);
            }
            {
                int krow = ks2 * 16 + (l & 15);
                int nb   = (wn2 * 16 + (l >> 4) * 8) * 2;
                uint32_t woff = SWZW((uint32_t)(krow * 256 + nb));
                uint32_t t4[4];
                ldm_x4_t(t4, sb + SM_W + woff);
                bh[0][0] = t4[0]; bh[0][1] = t4[1];
                bh[1][0] = t4[2]; bh[1][1] = t4[3];
                ldm_x4_t(t4, sb + SM_W + W_LO_OFF + woff);
                bl[0][0] = t4[0]; bl[0][1] = t4[1];
                bl[1][0] = t4[2]; bl[1][1] = t4[3];
            }
            #pragma unroll
            for (int nt = 0; nt < 2; nt++) mma_bf16(acc2[nt], ah, bh[nt]);
            #pragma unroll
            for (int nt = 0; nt < 2; nt++) mma_bf16(acc2[nt], ah, bl[nt]);
            #pragma unroll
            for (int nt = 0; nt < 2; nt++) mma_bf16(acc2[nt], al, bh[nt]);
        }
    };

    // ---- epilogue2g: H(64 rows) -> global P pairs at row base rb ----
    auto epilogue2g = [&](float (*acc2)[4], const float* sBias,
                          __nv_bfloat16* nHi, __nv_bfloat16* nLo, int rb) {
        #pragma unroll
        for (int nt = 0; nt < 2; nt++) {
            int c = wn2 * 16 + nt * 8 + (l & 3) * 2;
            #pragma unroll
            for (int half = 0; half < 2; half++) {
                int gm = wm2 * 16 + (l >> 2) + half * 8;
                float x0 = acc2[nt][half * 2]     + sBias[c];
                float x1 = acc2[nt][half * 2 + 1] + sBias[c + 1];
                float t0 = fast_tanh(x0), t1 = fast_tanh(x1);
                uint32_t hp = f2bf2(t0, t1);
                uint32_t lp = f2bf2(t0 - bf_lo(hp), t1 - bf_hi(hp));
                size_t base = (size_t)(rb + (gm >> 1)) * 256 + (size_t)((gm & 1) * 128 + c);
                *(uint32_t*)(nHi + base) = hp;
                *(uint32_t*)(nLo + base) = lp;
            }
        }
    };

    // ---- epilogue2s: H(<=64 rows) -> smem P; last level -> out ----
    auto epilogue2s = [&](float (*acc2)[4], const float* sBias, bool lastlv, int mrows) {
        if (wm2 * 16 >= mrows) return;
        #pragma unroll
        for (int nt = 0; nt < 2; nt++) {
            int c = wn2 * 16 + nt * 8 + (l & 3) * 2;
            #pragma unroll
            for (int half = 0; half < 2; half++) {
                int gm = wm2 * 16 + (l >> 2) + half * 8;
                float x0 = acc2[nt][half * 2]     + sBias[c];
                float x1 = acc2[nt][half * 2 + 1] + sBias[c + 1];
                float t0 = fast_tanh(x0), t1 = fast_tanh(x1);
                if (lastlv) {
                    if (gm == 0) { out[c] = t0; out[c + 1] = t1; }
                } else {
                    uint32_t hp = f2bf2(t0, t1);
                    uint32_t lp = f2bf2(t0 - bf_lo(hp), t1 - bf_hi(hp));
                    uint32_t off = SWZB((uint32_t)((gm >> 1) * 512 + ((gm & 1) * 128 + c) * 2));
                    *(uint32_t*)(smem + SM_S1 + off) = hp;
                    *(uint32_t*)(smem + SM_S2 + off) = lp;
                }
            }
        }
    };

    const float* sBin  = (const float*)(smem + SM_BIN);
    const float* sBsum = (const float*)(smem + SM_BSUM);

    // ============ PHASE L: leaf + level 1 fused ============
    for (int t = cta; t < NLV / 128; t += NCTA) {
        const int m0 = t * 128;
        for (int i = tid; i < 64 * 16; i += NT) {
            int kr = i >> 4, ch = i & 15;
            uint32_t off = SWZW((uint32_t)(kr * 256 + ch * 16));
            cp16(sb + SM_S1 + off, g_WIhi + (size_t)kr * 128 + ch * 8);
            cp16(sb + SM_S1 + 16384 + off, g_WIlo + (size_t)kr * 128 + ch * 8);
        }
        CP_COMMIT();
        for (int i = tid; i < 1024; i += NT) {
            int r = i >> 3, kg = i & 7;
            const float* src = leafX + (size_t)(m0 + r) * 64 + kg * 8;
            float4 f0 = *(const float4*)src;
            float4 f1 = *(const float4*)(src + 4);
            float xs[8] = {f0.x, f0.y, f0.z, f0.w, f1.x, f1.y, f1.z, f1.w};
            uint32_t hp[4], lp[4];
            #pragma unroll
            for (int j = 0; j < 4; j++) {
                hp[j] = f2bf2(xs[2 * j], xs[2 * j + 1]);
                lp[j] = f2bf2(xs[2 * j] - bf_lo(hp[j]), xs[2 * j + 1] - bf_hi(hp[j]));
            }
            uint32_t off = SWZA((uint32_t)(r * 128 + kg * 16));
            *(uint4*)(smem + SM_S0 + off)         = make_uint4(hp[0], hp[1], hp[2], hp[3]);
            *(uint4*)(smem + SM_S0 + 16384 + off) = make_uint4(lp[0], lp[1], lp[2], lp[3]);
        }
        CP_WAIT(0);
        __syncthreads();

        float acc[4][4];
        #pragma unroll
        for (int nt = 0; nt < 4; nt++)
            #pragma unroll
            for (int q = 0; q < 4; q++) acc[nt][q] = 0.f;
        compute_stage1(acc, sb + SM_S0, sb + SM_S1, 16384, 0);
        __syncthreads();
        epilogue1(acc, sBin);
        __syncthreads();

        float acc2[2][4];
        #pragma unroll
        for (int nt = 0; nt < 2; nt++)
            #pragma unroll
            for (int q = 0; q < 4; q++) acc2[nt][q] = 0.f;
        compute_g2(acc2, 64);
        __syncthreads();
        epilogue2g(acc2, sBsum, g_Ahi, g_Alo, t * 32);
    }
    unsigned bar = 1;
    grid_barrier(bar);

    // ============ PHASE D: 5 fused double-levels ============
    const __nv_bfloat16* cH = g_Ahi;
    const __nv_bfloat16* cL = g_Alo;
    int R = 65536;
    for (int d = 0; d < 5; d++) {
        __nv_bfloat16* nH = (cH == g_Ahi) ? g_Bhi : g_Ahi;
        __nv_bfloat16* nL = (cL == g_Alo) ? g_Blo : g_Alo;
        const int tiles = R >> 7;

        auto load_a = [&](int m0, int st, uint32_t slot) {
            for (int i = tid; i < 1024; i += NT) {
                int r = i >> 3, kg = i & 7;
                uint32_t off = SWZA((uint32_t)(r * 128 + kg * 16));
                size_t gi = (size_t)(m0 + r) * 256 + st * 64 + kg * 8;
                cp16(slot + off, cH + gi);
                cp16(slot + 16384 + off, cL + gi);
            }
        };

        bool first = true;
        for (int t = cta; t < tiles; t += NCTA) {
            const int m0 = t * 128;
            if (first) { load_a(m0, 0, sb + SM_S0); CP_COMMIT(); first = false; }
            load_a(m0, 1, sb + SM_S1); CP_COMMIT();
            load_a(m0, 2, sb + SM_S2); CP_COMMIT();

            float acc[4][4];
            #pragma unroll
            for (int nt = 0; nt < 4; nt++)
                #pragma unroll
                for (int q = 0; q < 4; q++) acc[nt][q] = 0.f;

            CP_WAIT(2); __syncthreads();
            compute_stage1(acc, sb + SM_S0, sb + SM_W, W_LO_OFF, 0);
            __syncthreads();
            load_a(m0, 3, sb + SM_S0); CP_COMMIT();
            CP_WAIT(2); __syncthreads();
            compute_stage1(acc, sb + SM_S1, sb + SM_W, W_LO_OFF, 1);
            __syncthreads();
            CP_WAIT(1); __syncthreads();
            compute_stage1(acc, sb + SM_S2, sb + SM_W, W_LO_OFF, 2);
            __syncthreads();
            CP_WAIT(0); __syncthreads();
            compute_stage1(acc, sb + SM_S0, sb + SM_W, W_LO_OFF, 3);
            __syncthreads();

            epilogue1(acc, sBsum);
            __syncthreads();

            // prefetch next tile's stage 0 into S0 while GEMM2 runs on S1/S2
            int tn = t + NCTA;
            if (tn < tiles) { load_a(tn * 128, 0, sb + SM_S0); CP_COMMIT(); }

            float acc2[2][4];
            #pragma unroll
            for (int nt = 0; nt < 2; nt++)
                #pragma unroll
                for (int q = 0; q < 4; q++) acc2[nt][q] = 0.f;
            compute_g2(acc2, 64);
            __syncthreads();
            epilogue2g(acc2, sBsum, nH, nL, t * 32);
        }
        grid_barrier(++bar);
        cH = nH; cL = nL; R >>= 2;
    }

    // ============ PHASE F: last 7 levels (64 -> root), single CTA ============
    if (cta == 0) {
        for (int i = tid; i < 64 * 32; i += NT) {
            int r = i >> 5, ch = i & 31;
            uint32_t off = SWZB((uint32_t)(r * 512 + ch * 16));
            cp16(sb + SM_S1 + off, cH + (size_t)r * 256 + ch * 8);
            cp16(sb + SM_S2 + off, cL + (size_t)r * 256 + ch * 8);
        }
        CP_COMMIT(); CP_WAIT(0);
        __syncthreads();
        int Mo = 64;
        for (int lv = 0; lv < 7; lv++) {
            float acc2[2][4];
            #pragma unroll
            for (int nt = 0; nt < 2; nt++)
                #pragma unroll
                for (int q = 0; q < 4; q++) acc2[nt][q] = 0.f;
            compute_g2(acc2, Mo);
            __syncthreads();
            epilogue2s(acc2, sBsum, lv == 6, Mo);
            __syncthreads();
            Mo >>= 1;
        }
    }
}

// ---------------- host ----------------
extern "C" void kernel_launch(void* const* d_in, const int* in_sizes, int n_in,
                              void* d_out, int out_size) {
    const float* leaf_x = (const float*)d_in[0];
    const float* W_in   = (const float*)d_in[1];
    const float* b_in   = (const float*)d_in[2];
    const float* W_l    = (const float*)d_in[3];
    const float* b_l    = (const float*)d_in[4];
    const float* W_r    = (const float*)d_in[5];
    const float* b_r    = (const float*)d_in[6];

    cudaFuncSetAttribute(rnn_all, cudaFuncAttributeMaxDynamicSharedMemorySize, SMEM_ALL);

    prep_kernel<<<64, 256>>>(W_in, b_in, W_l, b_l, W_r, b_r);
    rnn_all<<<NCTA, NT, SMEM_ALL>>>(leaf_x, (float*)d_out);
}